// round 16
// baseline (speedup 1.0000x reference)
#include <cuda_runtime.h>
#include <cuda_bf16.h>
#include <cstdint>

#define Bn 256
#define Sn 365
#define INn 5
#define SCAn 27
#define Hn 256
#define Mn (Bn*Sn)          // 93440, m = t*256 + b

typedef unsigned long long u64t;

// scratch (device globals; no runtime allocation)
__device__ float g_a[(size_t)Mn * Hn];        // sigmoid(sca@w_a^T + b_a)
__device__ float g_pre[(size_t)Mn * 4 * Hn];  // [m][gate i,f,o,g][256]

// R3-exact sigmoid (bitwise): __expf
__device__ __forceinline__ float sigf(float x) { return 1.0f / (1.0f + __expf(-x)); }

__device__ __forceinline__ u64t ffma2(u64t a, u64t b, u64t c) {
    u64t d; asm("fma.rn.f32x2 %0,%1,%2,%3;" : "=l"(d) : "l"(a), "l"(b), "l"(c));
    return d;
}
__device__ __forceinline__ u64t pk2(float x) {
    u64t r; asm("mov.b64 %0,{%1,%1};" : "=l"(r) : "f"(x)); return r;
}
__device__ __forceinline__ u64t pk2p(float x, float y) {
    u64t r; asm("mov.b64 %0,{%1,%2};" : "=l"(r) : "f"(x), "f"(y)); return r;
}
__device__ __forceinline__ float lo2(u64t v) {
    float a, b; asm("mov.b64 {%0,%1},%2;" : "=f"(a), "=f"(b) : "l"(v)); return a;
}
__device__ __forceinline__ float hi2(u64t v) {
    float a, b; asm("mov.b64 {%0,%1},%2;" : "=f"(a), "=f"(b) : "l"(v)); return b;
}

// ========================== Kernel A (verbatim R3) ==========================
__global__ __launch_bounds__(256) void kernelA(const float* __restrict__ xsca,
                                               const float* __restrict__ w_a,
                                               const float* __restrict__ b_a) {
    __shared__ float wsh[Hn * SCAn];
    __shared__ float ssh[64][28];
    int tid = threadIdx.x;
    int m0 = blockIdx.x * 64;
    for (int i = tid; i < Hn * SCAn; i += 256) wsh[i] = w_a[i];
    for (int i = tid; i < 64 * SCAn; i += 256) {
        int r = i / SCAn, k = i - r * SCAn;
        int m = m0 + r, t = m >> 8, b = m & 255;
        ssh[r][k] = xsca[((size_t)b * Sn + t) * SCAn + k];
    }
    __syncthreads();
    float wr[SCAn];
#pragma unroll
    for (int k = 0; k < SCAn; k++) wr[k] = wsh[tid * SCAn + k];
    float bias = b_a[tid];
    for (int r = 0; r < 64; r++) {
        float s = bias;
#pragma unroll
        for (int k = 0; k < SCAn; k++) s = fmaf(ssh[r][k], wr[k], s);
        g_a[(size_t)(m0 + r) * Hn + tid] = sigf(s);
    }
}

// ========================== Kernel B (verbatim R14) ==========================
__global__ __launch_bounds__(256) void kernelB(
    const float* __restrict__ xin,
    const float* __restrict__ w_ix, const float* __restrict__ w_ia, const float* __restrict__ b_i,
    const float* __restrict__ w_fx, const float* __restrict__ w_fa, const float* __restrict__ b_f,
    const float* __restrict__ w_ox, const float* __restrict__ w_oa, const float* __restrict__ b_o,
    const float* __restrict__ w_gx, const float* __restrict__ b_g)
{
    __shared__ __align__(16) float Ash[2][16][136];
    __shared__ __align__(16) float Bsh[2][16][136];
    __shared__ float Xs[128][6];
    __shared__ float Wxs[128][6];
    __shared__ float Bias[128];

    int ct = blockIdx.x, rt = blockIdx.y;
    int gate = ct >> 1, jg0 = (ct & 1) * 128;
    int tid = threadIdx.x, tx = tid & 15, ty = tid >> 4;
    int m0 = rt * 128;

    const float* wxp = (gate == 0) ? w_ix : (gate == 1) ? w_fx : (gate == 2) ? w_ox : w_gx;
    const float* wap = (gate == 0) ? w_ia : (gate == 1) ? w_fa : w_oa;
    const float* bp  = (gate == 0) ? b_i  : (gate == 1) ? b_f  : (gate == 2) ? b_o : b_g;

    for (int i = tid; i < 128 * INn; i += 256) {
        int r = i / INn, k = i - r * INn;
        int m = m0 + r, t = m >> 8, b = m & 255;
        Xs[r][k] = xin[((size_t)b * Sn + t) * INn + k];
    }
    for (int i = tid; i < 128 * INn; i += 256) {
        int c = i / INn, k = i - c * INn;
        Wxs[c][k] = wxp[(jg0 + c) * INn + k];
    }
    if (tid < 128) Bias[tid] = bp[jg0 + tid];

    u64t acc2[8][4];
#pragma unroll
    for (int i = 0; i < 8; i++)
#pragma unroll
        for (int jp = 0; jp < 4; jp++) acc2[i][jp] = 0ULL;

    if (gate < 3) {
        int r = tid >> 1, kq = (tid & 1) * 8;
        const float* sa = &g_a[(size_t)(m0 + r) * Hn + kq];
        const float* sb = &wap[(size_t)(jg0 + r) * Hn + kq];
        float4 a0 = *(const float4*)sa, a1 = *(const float4*)(sa + 4);
        float4 b0 = *(const float4*)sb, b1 = *(const float4*)(sb + 4);
        Ash[0][kq + 0][r] = a0.x; Ash[0][kq + 1][r] = a0.y; Ash[0][kq + 2][r] = a0.z; Ash[0][kq + 3][r] = a0.w;
        Ash[0][kq + 4][r] = a1.x; Ash[0][kq + 5][r] = a1.y; Ash[0][kq + 6][r] = a1.z; Ash[0][kq + 7][r] = a1.w;
        Bsh[0][kq + 0][r] = b0.x; Bsh[0][kq + 1][r] = b0.y; Bsh[0][kq + 2][r] = b0.z; Bsh[0][kq + 3][r] = b0.w;
        Bsh[0][kq + 4][r] = b1.x; Bsh[0][kq + 5][r] = b1.y; Bsh[0][kq + 6][r] = b1.z; Bsh[0][kq + 7][r] = b1.w;
        __syncthreads();
        for (int kt = 0; kt < 16; kt++) {
            int p = kt & 1;
            if (kt < 15) {
                const float* sa2 = sa + (kt + 1) * 16;
                const float* sb2 = sb + (kt + 1) * 16;
                a0 = *(const float4*)sa2; a1 = *(const float4*)(sa2 + 4);
                b0 = *(const float4*)sb2; b1 = *(const float4*)(sb2 + 4);
            }
#pragma unroll
            for (int kk = 0; kk < 16; kk++) {
                float4 x0 = *(const float4*)&Ash[p][kk][ty * 4];
                float4 x1 = *(const float4*)&Ash[p][kk][ty * 4 + 64];
                ulonglong2 yL = *(const ulonglong2*)&Bsh[p][kk][tx * 4];
                ulonglong2 yH = *(const ulonglong2*)&Bsh[p][kk][tx * 4 + 64];
                u64t ad[8] = {pk2(x0.x), pk2(x0.y), pk2(x0.z), pk2(x0.w),
                              pk2(x1.x), pk2(x1.y), pk2(x1.z), pk2(x1.w)};
                u64t bv[4] = {yL.x, yL.y, yH.x, yH.y};
#pragma unroll
                for (int i = 0; i < 8; i++)
#pragma unroll
                    for (int jp = 0; jp < 4; jp++)
                        acc2[i][jp] = ffma2(ad[i], bv[jp], acc2[i][jp]);
            }
            if (kt < 15) {
                int q = p ^ 1;
                Ash[q][kq + 0][r] = a0.x; Ash[q][kq + 1][r] = a0.y; Ash[q][kq + 2][r] = a0.z; Ash[q][kq + 3][r] = a0.w;
                Ash[q][kq + 4][r] = a1.x; Ash[q][kq + 5][r] = a1.y; Ash[q][kq + 6][r] = a1.z; Ash[q][kq + 7][r] = a1.w;
                Bsh[q][kq + 0][r] = b0.x; Bsh[q][kq + 1][r] = b0.y; Bsh[q][kq + 2][r] = b0.z; Bsh[q][kq + 3][r] = b0.w;
                Bsh[q][kq + 4][r] = b1.x; Bsh[q][kq + 5][r] = b1.y; Bsh[q][kq + 6][r] = b1.z; Bsh[q][kq + 7][r] = b1.w;
            }
            __syncthreads();
        }
    }
    __syncthreads();

#pragma unroll
    for (int i = 0; i < 8; i++) {
        int rr = ty * 4 + (i & 3) + ((i >> 2) * 64);
        float xr[INn];
#pragma unroll
        for (int k = 0; k < INn; k++) xr[k] = Xs[rr][k];
        float val[8];
#pragma unroll
        for (int j = 0; j < 8; j++) {
            int cc = tx * 4 + (j & 3) + ((j >> 2) * 64);
            float accv = (j & 1) ? hi2(acc2[i][j >> 1]) : lo2(acc2[i][j >> 1]);
            float s = accv + Bias[cc];
#pragma unroll
            for (int k = 0; k < INn; k++) s = fmaf(xr[k], Wxs[cc][k], s);
            val[j] = s;
        }
        size_t base = (size_t)(m0 + rr) * 1024 + ct * 128 + tx * 4;
        *(float4*)&g_pre[base]      = make_float4(val[0], val[1], val[2], val[3]);
        *(float4*)&g_pre[base + 64] = make_float4(val[4], val[5], val[6], val[7]);
    }
}

// ========================== Kernel C ==========================
// R14 pipeline; NEW stage layout [k-dim][batch] so each thread's 2 owned h
// values (adjacent batches) publish as ONE st.shared::cluster.b64 per peer
// (8 messages instead of 16). Matvec reads one broadcast LDS.128 = 4 batches
// per k; per-chain k order unchanged -> bitwise-identical.
#define STGOFF 32768
#define PARTOFF 40960
#define SMEMC_BYTES (43008 * 4)

__global__ __launch_bounds__(256, 1) __cluster_dims__(8, 1, 1)
void kernelC(const float* __restrict__ soil,
             const float* __restrict__ w_ih, const float* __restrict__ w_fo,
             const float* __restrict__ w_oh, const float* __restrict__ w_gh,
             float* __restrict__ out)
{
    extern __shared__ float smC[];
    int tid = threadIdx.x;
    int d = tid & 31, w = tid >> 5;
    int kh = w & 1, bg = w >> 1;
    unsigned rank; asm("mov.u32 %0, %%cluster_ctarank;" : "=r"(rank));
    int cl = blockIdx.x >> 3;
    int dimBase = (int)rank * 32;

    const float* wsrc0[4] = {w_ih, w_fo, w_oh, w_gh};
    for (int c = tid; c < 8192; c += 256) {
        int g = c >> 11, rem = c & 2047, dd = rem >> 6, kq = rem & 63;
        float4 v = *(const float4*)&wsrc0[g][(size_t)(dimBase + dd) * Hn + kq * 4];
        *(float4*)&smC[g * 8192 + dd * 256 + ((kq ^ (dd & 7)) << 2)] = v;
    }
    for (int i = tid; i < 8192; i += 256) smC[STGOFF + i] = 0.0f;
    __syncthreads();
    asm volatile("barrier.cluster.arrive.aligned;" ::: "memory");

    uint32_t smu;
    asm("{ .reg .u64 t0; cvta.to.shared.u64 t0, %1; cvt.u32.u64 %0, t0; }" : "=r"(smu) : "l"(smC));
    uint32_t stg_base = smu + STGOFF * 4;
    uint32_t peer[8];
#pragma unroll
    for (int rr = 0; rr < 8; rr++)
        asm("mapa.shared::cluster.u32 %0, %1, %2;" : "=r"(peer[rr]) : "r"(stg_base), "r"(rr));

    int b0 = bg * 4;
    int jo = 2 * kh;
    int gb0o = cl * 16 + b0 + jo;
    float cc[2] = {0,0}, sc[2] = {0,0}, sc2[2] = {0,0}, scs[2] = {0,0};
    float ss[2] = {0,0}, ss2[2] = {0,0};

    const size_t CO = (size_t)Bn * Sn * Hn;
    const float* Wd0 = &smC[0 * 8192 + d * 256];
    const float* Wd1 = &smC[1 * 8192 + d * 256];
    const float* Wd2 = &smC[2 * 8192 + d * 256];
    const float* Wd3 = &smC[3 * 8192 + d * 256];
    int dsw = d & 7;
    int kq0 = kh * 32;
    int barid = bg + 1;

    for (int t = 0; t < Sn; t++) {
        int pb = t & 1, nb = pb ^ 1;

        // prefetch own preacts + soil — BEFORE the wait (hides under skew)
        float pre[4][2], so[2];
#pragma unroll
        for (int jj = 0; jj < 2; jj++) {
            size_t mrow = ((size_t)t * 256 + gb0o + jj) * 1024 + dimBase + d;
#pragma unroll
            for (int g = 0; g < 4; g++) pre[g][jj] = g_pre[mrow + g * 256];
            so[jj] = soil[(size_t)(gb0o + jj) * Sn + t];
        }

        // Pearson factor from last step's sums — also pre-wait
        float n_f = fmaxf((float)t, 1.0f);
        float inv_n = 1.0f / n_f;
        float fac[2];
#pragma unroll
        for (int jj = 0; jj < 2; jj++) {
            float cov   = scs[jj] - sc[jj] * (ss[jj] * inv_n);
            float var_c = sc2[jj] - sc[jj] * sc[jj] * inv_n;
            float var_s = ss2[jj] - ss[jj] * ss[jj] * inv_n;
            float den2 = var_c * var_s;
            float r = 0.0f;
            if (den2 > 0.0f) {
                float den = sqrtf(den2);
                if (den > 1e-12f) r = cov / den;
            }
            fac[jj] = fabsf(r) + 1.0f;
        }

        asm volatile("barrier.cluster.wait.aligned;" ::: "memory");

        // matvec over my k-half; stage layout [k][16 batches]:
        // one broadcast LDS.128 per k covers my 4 batches; k order unchanged.
        float acc[4][4];
#pragma unroll
        for (int g = 0; g < 4; g++)
#pragma unroll
            for (int j = 0; j < 4; j++) acc[g][j] = 0.0f;

        const float* hb = &smC[STGOFF + pb * 4096];
#pragma unroll 8
        for (int kq = kq0; kq < kq0 + 32; kq++) {
            int o = (kq ^ dsw) << 2;
            float4 w0 = *(const float4*)&Wd0[o];
            float4 w1 = *(const float4*)&Wd1[o];
            float4 w2 = *(const float4*)&Wd2[o];
            float4 w3 = *(const float4*)&Wd3[o];
            float wk0[4] = {w0.x, w0.y, w0.z, w0.w};
            float wk1[4] = {w1.x, w1.y, w1.z, w1.w};
            float wk2[4] = {w2.x, w2.y, w2.z, w2.w};
            float wk3[4] = {w3.x, w3.y, w3.z, w3.w};
#pragma unroll
            for (int kk = 0; kk < 4; kk++) {
                float4 hv = *(const float4*)&hb[(4 * kq + kk) * 16 + b0];
                float hvv[4] = {hv.x, hv.y, hv.z, hv.w};
#pragma unroll
                for (int j = 0; j < 4; j++) {
                    acc[0][j] = fmaf(wk0[kk], hvv[j], acc[0][j]);
                    acc[1][j] = fmaf(wk1[kk], hvv[j], acc[1][j]);
                    acc[2][j] = fmaf(wk2[kk], hvv[j], acc[2][j]);
                    acc[3][j] = fmaf(wk3[kk], hvv[j], acc[3][j]);
                }
            }
        }

        // publish the partial pairs the PEER k-half warp owns (4 STS.64)
        {
            int jp0 = 2 - jo;
            float* pbase = &smC[PARTOFF + (size_t)((kh * 4 + bg) * 4) * 64 + d * 2];
#pragma unroll
            for (int g = 0; g < 4; g++)
                *(u64t*)&pbase[g * 64] = pk2p(acc[g][jp0], acc[g][jp0 + 1]);
        }
        asm volatile("bar.sync %0, 64;" :: "r"(barid) : "memory");

        // gather peer's partials; e = own + peer
        float e[4][2];
        {
            const float* qbase = &smC[PARTOFF + (size_t)(((1 - kh) * 4 + bg) * 4) * 64 + d * 2];
#pragma unroll
            for (int g = 0; g < 4; g++) {
                u64t v = *(const u64t*)&qbase[g * 64];
                e[g][0] = acc[g][jo] + lo2(v);
                e[g][1] = acc[g][jo + 1] + hi2(v);
            }
        }

        // fast epilogue: gates -> cn, hn (Pearson factor precomputed)
        float hn2[2], cn2[2];
#pragma unroll
        for (int jj = 0; jj < 2; jj++) {
            float iv = sigf(pre[0][jj] + e[0][jj]);
            float fv = sigf(pre[1][jj] + e[1][jj]);
            float ov = sigf(pre[2][jj] + e[2][jj]);
            float gv = tanhf(pre[3][jj] + e[3][jj]);
            float c_raw = fv * cc[jj] + iv * gv;
            hn2[jj] = ov * tanhf(c_raw);
            cn2[jj] = c_raw * fac[jj];
        }
        // broadcast h pair to all 8 CTAs' stage[nb]: ONE b64 per peer
        {
            u64t hp = pk2p(hn2[0], hn2[1]);
            uint32_t soff = (uint32_t)((nb * 4096 + (dimBase + d) * 16 + b0 + jo) * 4);
#pragma unroll
            for (int rr = 0; rr < 8; rr++)
                asm volatile("st.shared::cluster.b64 [%0], %1;" :: "r"(peer[rr] + soff), "l"(hp) : "memory");
        }
        asm volatile("barrier.cluster.arrive.aligned;" ::: "memory");

        // DEFERRED: sums update + output STG
#pragma unroll
        for (int jj = 0; jj < 2; jj++) {
            float cn = cn2[jj];
            cc[jj] = cn;
            sc[jj] += cn; sc2[jj] = fmaf(cn, cn, sc2[jj]); scs[jj] = fmaf(cn, so[jj], scs[jj]);
            ss[jj] += so[jj]; ss2[jj] = fmaf(so[jj], so[jj], ss2[jj]);
            size_t oidx = ((size_t)(gb0o + jj) * Sn + t) * Hn + dimBase + d;
            out[oidx] = hn2[jj];
            out[CO + oidx] = cn;
        }
    }
    asm volatile("barrier.cluster.wait.aligned;" ::: "memory");
}

// ========================== launcher (serial) ==========================
extern "C" void kernel_launch(void* const* d_in, const int* in_sizes, int n_in,
                              void* d_out, int out_size) {
    const float* x_input = (const float*)d_in[0];
    const float* x_sca   = (const float*)d_in[1];
    const float* soil    = (const float*)d_in[2];
    const float* w_ix = (const float*)d_in[3];
    const float* w_ih = (const float*)d_in[4];
    const float* w_ia = (const float*)d_in[5];
    const float* b_i  = (const float*)d_in[6];
    const float* w_fx = (const float*)d_in[7];
    const float* w_fo = (const float*)d_in[8];
    const float* w_fa = (const float*)d_in[9];
    const float* b_f  = (const float*)d_in[10];
    const float* w_ox = (const float*)d_in[11];
    const float* w_oh = (const float*)d_in[12];
    const float* w_oa = (const float*)d_in[13];
    const float* b_o  = (const float*)d_in[14];
    const float* w_gx = (const float*)d_in[15];
    const float* w_gh = (const float*)d_in[16];
    const float* b_g  = (const float*)d_in[17];
    const float* w_a  = (const float*)d_in[18];
    const float* b_a  = (const float*)d_in[19];
    float* out = (float*)d_out;

    kernelA<<<Mn / 64, 256>>>(x_sca, w_a, b_a);
    dim3 gB(8, Mn / 128);
    kernelB<<<gB, 256>>>(x_input, w_ix, w_ia, b_i, w_fx, w_fa, b_f,
                         w_ox, w_oa, b_o, w_gx, b_g);
    cudaFuncSetAttribute(kernelC, cudaFuncAttributeMaxDynamicSharedMemorySize, SMEMC_BYTES);
    kernelC<<<128, 256, SMEMC_BYTES>>>(soil, w_ih, w_fo, w_oh, w_gh, out);
}

// round 17
// speedup vs baseline: 1.2192x; 1.2192x over previous
#include <cuda_runtime.h>
#include <cuda_bf16.h>
#include <cstdint>

#define Bn 256
#define Sn 365
#define INn 5
#define SCAn 27
#define Hn 256
#define Mn (Bn*Sn)          // 93440, m = t*256 + b

typedef unsigned long long u64t;

// scratch (device globals; no runtime allocation)
__device__ float g_a[(size_t)Mn * Hn];        // sigmoid(sca@w_a^T + b_a)
__device__ float g_pre[(size_t)Mn * 4 * Hn];  // [m][gate i,f,o,g][256]

// R3-exact sigmoid (bitwise): __expf
__device__ __forceinline__ float sigf(float x) { return 1.0f / (1.0f + __expf(-x)); }

__device__ __forceinline__ u64t ffma2(u64t a, u64t b, u64t c) {
    u64t d; asm("fma.rn.f32x2 %0,%1,%2,%3;" : "=l"(d) : "l"(a), "l"(b), "l"(c));
    return d;
}
__device__ __forceinline__ u64t pk2(float x) {
    u64t r; asm("mov.b64 %0,{%1,%1};" : "=l"(r) : "f"(x)); return r;
}
__device__ __forceinline__ u64t pk2p(float x, float y) {
    u64t r; asm("mov.b64 %0,{%1,%2};" : "=l"(r) : "f"(x), "f"(y)); return r;
}
__device__ __forceinline__ float lo2(u64t v) {
    float a, b; asm("mov.b64 {%0,%1},%2;" : "=f"(a), "=f"(b) : "l"(v)); return a;
}
__device__ __forceinline__ float hi2(u64t v) {
    float a, b; asm("mov.b64 {%0,%1},%2;" : "=f"(a), "=f"(b) : "l"(v)); return b;
}

// ========================== Kernel A (verbatim R3) ==========================
__global__ __launch_bounds__(256) void kernelA(const float* __restrict__ xsca,
                                               const float* __restrict__ w_a,
                                               const float* __restrict__ b_a) {
    __shared__ float wsh[Hn * SCAn];
    __shared__ float ssh[64][28];
    int tid = threadIdx.x;
    int m0 = blockIdx.x * 64;
    for (int i = tid; i < Hn * SCAn; i += 256) wsh[i] = w_a[i];
    for (int i = tid; i < 64 * SCAn; i += 256) {
        int r = i / SCAn, k = i - r * SCAn;
        int m = m0 + r, t = m >> 8, b = m & 255;
        ssh[r][k] = xsca[((size_t)b * Sn + t) * SCAn + k];
    }
    __syncthreads();
    float wr[SCAn];
#pragma unroll
    for (int k = 0; k < SCAn; k++) wr[k] = wsh[tid * SCAn + k];
    float bias = b_a[tid];
    for (int r = 0; r < 64; r++) {
        float s = bias;
#pragma unroll
        for (int k = 0; k < SCAn; k++) s = fmaf(ssh[r][k], wr[k], s);
        g_a[(size_t)(m0 + r) * Hn + tid] = sigf(s);
    }
}

// ========================== Kernel B (verbatim R14) ==========================
__global__ __launch_bounds__(256) void kernelB(
    const float* __restrict__ xin,
    const float* __restrict__ w_ix, const float* __restrict__ w_ia, const float* __restrict__ b_i,
    const float* __restrict__ w_fx, const float* __restrict__ w_fa, const float* __restrict__ b_f,
    const float* __restrict__ w_ox, const float* __restrict__ w_oa, const float* __restrict__ b_o,
    const float* __restrict__ w_gx, const float* __restrict__ b_g)
{
    __shared__ __align__(16) float Ash[2][16][136];
    __shared__ __align__(16) float Bsh[2][16][136];
    __shared__ float Xs[128][6];
    __shared__ float Wxs[128][6];
    __shared__ float Bias[128];

    int ct = blockIdx.x, rt = blockIdx.y;
    int gate = ct >> 1, jg0 = (ct & 1) * 128;
    int tid = threadIdx.x, tx = tid & 15, ty = tid >> 4;
    int m0 = rt * 128;

    const float* wxp = (gate == 0) ? w_ix : (gate == 1) ? w_fx : (gate == 2) ? w_ox : w_gx;
    const float* wap = (gate == 0) ? w_ia : (gate == 1) ? w_fa : w_oa;
    const float* bp  = (gate == 0) ? b_i  : (gate == 1) ? b_f  : (gate == 2) ? b_o : b_g;

    for (int i = tid; i < 128 * INn; i += 256) {
        int r = i / INn, k = i - r * INn;
        int m = m0 + r, t = m >> 8, b = m & 255;
        Xs[r][k] = xin[((size_t)b * Sn + t) * INn + k];
    }
    for (int i = tid; i < 128 * INn; i += 256) {
        int c = i / INn, k = i - c * INn;
        Wxs[c][k] = wxp[(jg0 + c) * INn + k];
    }
    if (tid < 128) Bias[tid] = bp[jg0 + tid];

    u64t acc2[8][4];
#pragma unroll
    for (int i = 0; i < 8; i++)
#pragma unroll
        for (int jp = 0; jp < 4; jp++) acc2[i][jp] = 0ULL;

    if (gate < 3) {
        int r = tid >> 1, kq = (tid & 1) * 8;
        const float* sa = &g_a[(size_t)(m0 + r) * Hn + kq];
        const float* sb = &wap[(size_t)(jg0 + r) * Hn + kq];
        float4 a0 = *(const float4*)sa, a1 = *(const float4*)(sa + 4);
        float4 b0 = *(const float4*)sb, b1 = *(const float4*)(sb + 4);
        Ash[0][kq + 0][r] = a0.x; Ash[0][kq + 1][r] = a0.y; Ash[0][kq + 2][r] = a0.z; Ash[0][kq + 3][r] = a0.w;
        Ash[0][kq + 4][r] = a1.x; Ash[0][kq + 5][r] = a1.y; Ash[0][kq + 6][r] = a1.z; Ash[0][kq + 7][r] = a1.w;
        Bsh[0][kq + 0][r] = b0.x; Bsh[0][kq + 1][r] = b0.y; Bsh[0][kq + 2][r] = b0.z; Bsh[0][kq + 3][r] = b0.w;
        Bsh[0][kq + 4][r] = b1.x; Bsh[0][kq + 5][r] = b1.y; Bsh[0][kq + 6][r] = b1.z; Bsh[0][kq + 7][r] = b1.w;
        __syncthreads();
        for (int kt = 0; kt < 16; kt++) {
            int p = kt & 1;
            if (kt < 15) {
                const float* sa2 = sa + (kt + 1) * 16;
                const float* sb2 = sb + (kt + 1) * 16;
                a0 = *(const float4*)sa2; a1 = *(const float4*)(sa2 + 4);
                b0 = *(const float4*)sb2; b1 = *(const float4*)(sb2 + 4);
            }
#pragma unroll
            for (int kk = 0; kk < 16; kk++) {
                float4 x0 = *(const float4*)&Ash[p][kk][ty * 4];
                float4 x1 = *(const float4*)&Ash[p][kk][ty * 4 + 64];
                ulonglong2 yL = *(const ulonglong2*)&Bsh[p][kk][tx * 4];
                ulonglong2 yH = *(const ulonglong2*)&Bsh[p][kk][tx * 4 + 64];
                u64t ad[8] = {pk2(x0.x), pk2(x0.y), pk2(x0.z), pk2(x0.w),
                              pk2(x1.x), pk2(x1.y), pk2(x1.z), pk2(x1.w)};
                u64t bv[4] = {yL.x, yL.y, yH.x, yH.y};
#pragma unroll
                for (int i = 0; i < 8; i++)
#pragma unroll
                    for (int jp = 0; jp < 4; jp++)
                        acc2[i][jp] = ffma2(ad[i], bv[jp], acc2[i][jp]);
            }
            if (kt < 15) {
                int q = p ^ 1;
                Ash[q][kq + 0][r] = a0.x; Ash[q][kq + 1][r] = a0.y; Ash[q][kq + 2][r] = a0.z; Ash[q][kq + 3][r] = a0.w;
                Ash[q][kq + 4][r] = a1.x; Ash[q][kq + 5][r] = a1.y; Ash[q][kq + 6][r] = a1.z; Ash[q][kq + 7][r] = a1.w;
                Bsh[q][kq + 0][r] = b0.x; Bsh[q][kq + 1][r] = b0.y; Bsh[q][kq + 2][r] = b0.z; Bsh[q][kq + 3][r] = b0.w;
                Bsh[q][kq + 4][r] = b1.x; Bsh[q][kq + 5][r] = b1.y; Bsh[q][kq + 6][r] = b1.z; Bsh[q][kq + 7][r] = b1.w;
            }
            __syncthreads();
        }
    }
    __syncthreads();

#pragma unroll
    for (int i = 0; i < 8; i++) {
        int rr = ty * 4 + (i & 3) + ((i >> 2) * 64);
        float xr[INn];
#pragma unroll
        for (int k = 0; k < INn; k++) xr[k] = Xs[rr][k];
        float val[8];
#pragma unroll
        for (int j = 0; j < 8; j++) {
            int cc = tx * 4 + (j & 3) + ((j >> 2) * 64);
            float accv = (j & 1) ? hi2(acc2[i][j >> 1]) : lo2(acc2[i][j >> 1]);
            float s = accv + Bias[cc];
#pragma unroll
            for (int k = 0; k < INn; k++) s = fmaf(xr[k], Wxs[cc][k], s);
            val[j] = s;
        }
        size_t base = (size_t)(m0 + rr) * 1024 + ct * 128 + tx * 4;
        *(float4*)&g_pre[base]      = make_float4(val[0], val[1], val[2], val[3]);
        *(float4*)&g_pre[base + 64] = make_float4(val[4], val[5], val[6], val[7]);
    }
}

// ========================== Kernel C ==========================
// R14 pipeline; stage layout = [pair(8)][k(256)][2] (batch-pair interleaved):
//  - writer: ONE st.shared::cluster.b64 per peer, lane stride 8B (conflict-free)
//  - reader: 4 broadcast LDS.128 per kq (same count as R14); per-chain k order
//    strictly ascending == R3 -> bitwise-identical trajectory.
#define STGOFF 32768
#define PARTOFF 40960
#define SMEMC_BYTES (43008 * 4)

__global__ __launch_bounds__(256, 1) __cluster_dims__(8, 1, 1)
void kernelC(const float* __restrict__ soil,
             const float* __restrict__ w_ih, const float* __restrict__ w_fo,
             const float* __restrict__ w_oh, const float* __restrict__ w_gh,
             float* __restrict__ out)
{
    extern __shared__ float smC[];
    int tid = threadIdx.x;
    int d = tid & 31, w = tid >> 5;
    int kh = w & 1, bg = w >> 1;
    unsigned rank; asm("mov.u32 %0, %%cluster_ctarank;" : "=r"(rank));
    int cl = blockIdx.x >> 3;
    int dimBase = (int)rank * 32;

    const float* wsrc0[4] = {w_ih, w_fo, w_oh, w_gh};
    for (int c = tid; c < 8192; c += 256) {
        int g = c >> 11, rem = c & 2047, dd = rem >> 6, kq = rem & 63;
        float4 v = *(const float4*)&wsrc0[g][(size_t)(dimBase + dd) * Hn + kq * 4];
        *(float4*)&smC[g * 8192 + dd * 256 + ((kq ^ (dd & 7)) << 2)] = v;
    }
    for (int i = tid; i < 8192; i += 256) smC[STGOFF + i] = 0.0f;
    __syncthreads();
    asm volatile("barrier.cluster.arrive.aligned;" ::: "memory");

    uint32_t smu;
    asm("{ .reg .u64 t0; cvta.to.shared.u64 t0, %1; cvt.u32.u64 %0, t0; }" : "=r"(smu) : "l"(smC));
    uint32_t stg_base = smu + STGOFF * 4;
    uint32_t peer[8];
#pragma unroll
    for (int rr = 0; rr < 8; rr++)
        asm("mapa.shared::cluster.u32 %0, %1, %2;" : "=r"(peer[rr]) : "r"(stg_base), "r"(rr));

    int b0 = bg * 4;
    int pr0 = b0 >> 1;               // first batch-pair index of this quartet
    int jo = 2 * kh;
    int gb0o = cl * 16 + b0 + jo;
    float cc[2] = {0,0}, sc[2] = {0,0}, sc2[2] = {0,0}, scs[2] = {0,0};
    float ss[2] = {0,0}, ss2[2] = {0,0};

    const size_t CO = (size_t)Bn * Sn * Hn;
    const float* Wd0 = &smC[0 * 8192 + d * 256];
    const float* Wd1 = &smC[1 * 8192 + d * 256];
    const float* Wd2 = &smC[2 * 8192 + d * 256];
    const float* Wd3 = &smC[3 * 8192 + d * 256];
    int dsw = d & 7;
    int kq0 = kh * 32;
    int barid = bg + 1;

    for (int t = 0; t < Sn; t++) {
        int pb = t & 1, nb = pb ^ 1;

        // prefetch own preacts + soil — BEFORE the wait (hides under skew)
        float pre[4][2], so[2];
#pragma unroll
        for (int jj = 0; jj < 2; jj++) {
            size_t mrow = ((size_t)t * 256 + gb0o + jj) * 1024 + dimBase + d;
#pragma unroll
            for (int g = 0; g < 4; g++) pre[g][jj] = g_pre[mrow + g * 256];
            so[jj] = soil[(size_t)(gb0o + jj) * Sn + t];
        }

        // Pearson factor from last step's sums — also pre-wait
        float n_f = fmaxf((float)t, 1.0f);
        float inv_n = 1.0f / n_f;
        float fac[2];
#pragma unroll
        for (int jj = 0; jj < 2; jj++) {
            float cov   = scs[jj] - sc[jj] * (ss[jj] * inv_n);
            float var_c = sc2[jj] - sc[jj] * sc[jj] * inv_n;
            float var_s = ss2[jj] - ss[jj] * ss[jj] * inv_n;
            float den2 = var_c * var_s;
            float r = 0.0f;
            if (den2 > 0.0f) {
                float den = sqrtf(den2);
                if (den > 1e-12f) r = cov / den;
            }
            fac[jj] = fabsf(r) + 1.0f;
        }

        asm volatile("barrier.cluster.wait.aligned;" ::: "memory");

        // matvec over my k-half; stage [pair][k][2] layout:
        // per kq: 2 float4 per pair = {hA(k),hB(k),hA(k+1),hB(k+1)}, k ascending.
        float acc[4][4];
#pragma unroll
        for (int g = 0; g < 4; g++)
#pragma unroll
            for (int j = 0; j < 4; j++) acc[g][j] = 0.0f;

        const float* hb = &smC[STGOFF + pb * 4096];
        const float* hpA = &hb[pr0 * 512];
        const float* hpB = &hb[(pr0 + 1) * 512];
#pragma unroll 8
        for (int kq = kq0; kq < kq0 + 32; kq++) {
            int o = (kq ^ dsw) << 2;
            float4 w0 = *(const float4*)&Wd0[o];
            float4 w1 = *(const float4*)&Wd1[o];
            float4 w2 = *(const float4*)&Wd2[o];
            float4 w3 = *(const float4*)&Wd3[o];
            float4 hA0 = *(const float4*)&hpA[kq * 8];       // b0,b1 @ k0,k1
            float4 hA1 = *(const float4*)&hpA[kq * 8 + 4];   // b0,b1 @ k2,k3
            float4 hB0 = *(const float4*)&hpB[kq * 8];       // b2,b3 @ k0,k1
            float4 hB1 = *(const float4*)&hpB[kq * 8 + 4];   // b2,b3 @ k2,k3
            // chain order per (g,j): k0,k1,k2,k3 (exactly R3)
            acc[0][0] = fmaf(w0.x, hA0.x, acc[0][0]); acc[0][0] = fmaf(w0.y, hA0.z, acc[0][0]);
            acc[0][0] = fmaf(w0.z, hA1.x, acc[0][0]); acc[0][0] = fmaf(w0.w, hA1.z, acc[0][0]);
            acc[0][1] = fmaf(w0.x, hA0.y, acc[0][1]); acc[0][1] = fmaf(w0.y, hA0.w, acc[0][1]);
            acc[0][1] = fmaf(w0.z, hA1.y, acc[0][1]); acc[0][1] = fmaf(w0.w, hA1.w, acc[0][1]);
            acc[0][2] = fmaf(w0.x, hB0.x, acc[0][2]); acc[0][2] = fmaf(w0.y, hB0.z, acc[0][2]);
            acc[0][2] = fmaf(w0.z, hB1.x, acc[0][2]); acc[0][2] = fmaf(w0.w, hB1.z, acc[0][2]);
            acc[0][3] = fmaf(w0.x, hB0.y, acc[0][3]); acc[0][3] = fmaf(w0.y, hB0.w, acc[0][3]);
            acc[0][3] = fmaf(w0.z, hB1.y, acc[0][3]); acc[0][3] = fmaf(w0.w, hB1.w, acc[0][3]);
            acc[1][0] = fmaf(w1.x, hA0.x, acc[1][0]); acc[1][0] = fmaf(w1.y, hA0.z, acc[1][0]);
            acc[1][0] = fmaf(w1.z, hA1.x, acc[1][0]); acc[1][0] = fmaf(w1.w, hA1.z, acc[1][0]);
            acc[1][1] = fmaf(w1.x, hA0.y, acc[1][1]); acc[1][1] = fmaf(w1.y, hA0.w, acc[1][1]);
            acc[1][1] = fmaf(w1.z, hA1.y, acc[1][1]); acc[1][1] = fmaf(w1.w, hA1.w, acc[1][1]);
            acc[1][2] = fmaf(w1.x, hB0.x, acc[1][2]); acc[1][2] = fmaf(w1.y, hB0.w == hB0.w ? hB0.z : hB0.z, acc[1][2]);
            acc[1][2] = fmaf(w1.z, hB1.x, acc[1][2]); acc[1][2] = fmaf(w1.w, hB1.z, acc[1][2]);
            acc[1][3] = fmaf(w1.x, hB0.y, acc[1][3]); acc[1][3] = fmaf(w1.y, hB0.w, acc[1][3]);
            acc[1][3] = fmaf(w1.z, hB1.y, acc[1][3]); acc[1][3] = fmaf(w1.w, hB1.w, acc[1][3]);
            acc[2][0] = fmaf(w2.x, hA0.x, acc[2][0]); acc[2][0] = fmaf(w2.y, hA0.z, acc[2][0]);
            acc[2][0] = fmaf(w2.z, hA1.x, acc[2][0]); acc[2][0] = fmaf(w2.w, hA1.z, acc[2][0]);
            acc[2][1] = fmaf(w2.x, hA0.y, acc[2][1]); acc[2][1] = fmaf(w2.y, hA0.w, acc[2][1]);
            acc[2][1] = fmaf(w2.z, hA1.y, acc[2][1]); acc[2][1] = fmaf(w2.w, hA1.w, acc[2][1]);
            acc[2][2] = fmaf(w2.x, hB0.x, acc[2][2]); acc[2][2] = fmaf(w2.y, hB0.z, acc[2][2]);
            acc[2][2] = fmaf(w2.z, hB1.x, acc[2][2]); acc[2][2] = fmaf(w2.w, hB1.z, acc[2][2]);
            acc[2][3] = fmaf(w2.x, hB0.y, acc[2][3]); acc[2][3] = fmaf(w2.y, hB0.w, acc[2][3]);
            acc[2][3] = fmaf(w2.z, hB1.y, acc[2][3]); acc[2][3] = fmaf(w2.w, hB1.w, acc[2][3]);
            acc[3][0] = fmaf(w3.x, hA0.x, acc[3][0]); acc[3][0] = fmaf(w3.y, hA0.z, acc[3][0]);
            acc[3][0] = fmaf(w3.z, hA1.x, acc[3][0]); acc[3][0] = fmaf(w3.w, hA1.z, acc[3][0]);
            acc[3][1] = fmaf(w3.x, hA0.y, acc[3][1]); acc[3][1] = fmaf(w3.y, hA0.w, acc[3][1]);
            acc[3][1] = fmaf(w3.z, hA1.y, acc[3][1]); acc[3][1] = fmaf(w3.w, hA1.w, acc[3][1]);
            acc[3][2] = fmaf(w3.x, hB0.x, acc[3][2]); acc[3][2] = fmaf(w3.y, hB0.z, acc[3][2]);
            acc[3][2] = fmaf(w3.z, hB1.x, acc[3][2]); acc[3][2] = fmaf(w3.w, hB1.z, acc[3][2]);
            acc[3][3] = fmaf(w3.x, hB0.y, acc[3][3]); acc[3][3] = fmaf(w3.y, hB0.w, acc[3][3]);
            acc[3][3] = fmaf(w3.z, hB1.y, acc[3][3]); acc[3][3] = fmaf(w3.w, hB1.w, acc[3][3]);
        }

        // publish the partial pairs the PEER k-half warp owns (4 STS.64)
        {
            int jp0 = 2 - jo;
            float* pbase = &smC[PARTOFF + (size_t)((kh * 4 + bg) * 4) * 64 + d * 2];
#pragma unroll
            for (int g = 0; g < 4; g++)
                *(u64t*)&pbase[g * 64] = pk2p(acc[g][jp0], acc[g][jp0 + 1]);
        }
        asm volatile("bar.sync %0, 64;" :: "r"(barid) : "memory");

        // gather peer's partials; e = own + peer
        float e[4][2];
        {
            const float* qbase = &smC[PARTOFF + (size_t)(((1 - kh) * 4 + bg) * 4) * 64 + d * 2];
#pragma unroll
            for (int g = 0; g < 4; g++) {
                u64t v = *(const u64t*)&qbase[g * 64];
                e[g][0] = acc[g][jo] + lo2(v);
                e[g][1] = acc[g][jo + 1] + hi2(v);
            }
        }

        // fast epilogue: gates -> cn, hn (Pearson factor precomputed)
        float hn2[2], cn2[2];
#pragma unroll
        for (int jj = 0; jj < 2; jj++) {
            float iv = sigf(pre[0][jj] + e[0][jj]);
            float fv = sigf(pre[1][jj] + e[1][jj]);
            float ov = sigf(pre[2][jj] + e[2][jj]);
            float gv = tanhf(pre[3][jj] + e[3][jj]);
            float c_raw = fv * cc[jj] + iv * gv;
            hn2[jj] = ov * tanhf(c_raw);
            cn2[jj] = c_raw * fac[jj];
        }
        // broadcast owned h pair: ONE conflict-free b64 per peer
        {
            u64t hp = pk2p(hn2[0], hn2[1]);
            uint32_t soff = (uint32_t)((nb * 4096 + (pr0 + kh) * 512 + (dimBase + d) * 2) * 4);
#pragma unroll
            for (int rr = 0; rr < 8; rr++)
                asm volatile("st.shared::cluster.b64 [%0], %1;" :: "r"(peer[rr] + soff), "l"(hp) : "memory");
        }
        asm volatile("barrier.cluster.arrive.aligned;" ::: "memory");

        // DEFERRED: sums update + output STG
#pragma unroll
        for (int jj = 0; jj < 2; jj++) {
            float cn = cn2[jj];
            cc[jj] = cn;
            sc[jj] += cn; sc2[jj] = fmaf(cn, cn, sc2[jj]); scs[jj] = fmaf(cn, so[jj], scs[jj]);
            ss[jj] += so[jj]; ss2[jj] = fmaf(so[jj], so[jj], ss2[jj]);
            size_t oidx = ((size_t)(gb0o + jj) * Sn + t) * Hn + dimBase + d;
            out[oidx] = hn2[jj];
            out[CO + oidx] = cn;
        }
    }
    asm volatile("barrier.cluster.wait.aligned;" ::: "memory");
}

// ========================== launcher (serial) ==========================
extern "C" void kernel_launch(void* const* d_in, const int* in_sizes, int n_in,
                              void* d_out, int out_size) {
    const float* x_input = (const float*)d_in[0];
    const float* x_sca   = (const float*)d_in[1];
    const float* soil    = (const float*)d_in[2];
    const float* w_ix = (const float*)d_in[3];
    const float* w_ih = (const float*)d_in[4];
    const float* w_ia = (const float*)d_in[5];
    const float* b_i  = (const float*)d_in[6];
    const float* w_fx = (const float*)d_in[7];
    const float* w_fo = (const float*)d_in[8];
    const float* w_fa = (const float*)d_in[9];
    const float* b_f  = (const float*)d_in[10];
    const float* w_ox = (const float*)d_in[11];
    const float* w_oh = (const float*)d_in[12];
    const float* w_oa = (const float*)d_in[13];
    const float* b_o  = (const float*)d_in[14];
    const float* w_gx = (const float*)d_in[15];
    const float* w_gh = (const float*)d_in[16];
    const float* b_g  = (const float*)d_in[17];
    const float* w_a  = (const float*)d_in[18];
    const float* b_a  = (const float*)d_in[19];
    float* out = (float*)d_out;

    kernelA<<<Mn / 64, 256>>>(x_sca, w_a, b_a);
    dim3 gB(8, Mn / 128);
    kernelB<<<gB, 256>>>(x_input, w_ix, w_ia, b_i, w_fx, w_fa, b_f,
                         w_ox, w_oa, b_o, w_gx, b_g);
    cudaFuncSetAttribute(kernelC, cudaFuncAttributeMaxDynamicSharedMemorySize, SMEMC_BYTES);
    kernelC<<<128, 256, SMEMC_BYTES>>>(soil, w_ih, w_fo, w_oh, w_gh, out);
}